// round 16
// baseline (speedup 1.0000x reference)
#include <cuda_runtime.h>

#define B_  16
#define NK_ 256
#define NQ_ 256
#define DK_ 256
#define H_  128
#define DV_ 256
#define KT  4     // k-rows per attn tile
#define RT  8     // rows per qproj block

// scratch (allocation-free rule: device globals). kproj no longer exists:
// it is computed inside the attn block that owns it.
__device__ float g_qproj[B_ * NQ_ * H_];   // (B, NQ, H)

__device__ __forceinline__ float tanh_fast(float x) {
    float y;
    asm("tanh.approx.f32 %0, %1;" : "=f"(y) : "f"(x));
    return y;
}

// ---------------------------------------------------------------------------
// Kernel A: qproj ONLY (R9 champion proj body, query arm).
// Rows with q >= valid_lens[b] are never read by attn -> early exit.
// ---------------------------------------------------------------------------
__global__ __launch_bounds__(128)
void qproj_kernel(const float* __restrict__ query,
                  const float* __restrict__ Wq,
                  const int*   __restrict__ valid_lens) {
    const int r0 = blockIdx.x * RT;

    const int vl = valid_lens[r0 >> 8];
    if ((r0 & (NQ_ - 1)) >= vl) return;    // whole row-range masked

    __shared__ __align__(16) float rowsT[DK_ * RT];      // rowsT[d*RT + r]
    const int t = threadIdx.x;             // 0..127

    {
        const float* src = query + (size_t)r0 * DK_;
        int r = t >> 4;
        int d0 = (t & 15) * 16;
        #pragma unroll
        for (int i = 0; i < 4; ++i) {
            float4 v = *reinterpret_cast<const float4*>(src + r * DK_ + d0 + i * 4);
            rowsT[(d0 + i * 4 + 0) * RT + r] = v.x;
            rowsT[(d0 + i * 4 + 1) * RT + r] = v.y;
            rowsT[(d0 + i * 4 + 2) * RT + r] = v.z;
            rowsT[(d0 + i * 4 + 3) * RT + r] = v.w;
        }
    }
    __syncthreads();

    float acc[RT];
    #pragma unroll
    for (int r = 0; r < RT; ++r) acc[r] = 0.f;

    #pragma unroll 4
    for (int d = 0; d < DK_; ++d) {
        float w = Wq[d * H_ + t];
        float4 ra = *reinterpret_cast<const float4*>(&rowsT[d * RT]);
        float4 rb = *reinterpret_cast<const float4*>(&rowsT[d * RT + 4]);
        acc[0] = fmaf(ra.x, w, acc[0]);
        acc[1] = fmaf(ra.y, w, acc[1]);
        acc[2] = fmaf(ra.z, w, acc[2]);
        acc[3] = fmaf(ra.w, w, acc[3]);
        acc[4] = fmaf(rb.x, w, acc[4]);
        acc[5] = fmaf(rb.y, w, acc[5]);
        acc[6] = fmaf(rb.z, w, acc[6]);
        acc[7] = fmaf(rb.w, w, acc[7]);
    }

    #pragma unroll
    for (int r = 0; r < RT; ++r)
        g_qproj[(size_t)(r0 + r) * H_ + t] = acc[r];
}

// ---------------------------------------------------------------------------
// Kernel B: R9 champion body + FUSED kproj prologue.
// The 4 kproj rows this tile needs are used ONLY here, so compute them
// in-block: stage key rows transposed (keyT[d*4+k], overlaid on the attnT
// buffer), then thread (h = t&127, kk = (t>>7)*2) accumulates 2 kproj values
// over d (coalesced Wk LDG + broadcast LDS.64 + 2 FMA). This FMA/LSU work
// hides under attn's MUFU/latency slack instead of costing proj wall time.
// ---------------------------------------------------------------------------
__global__ __launch_bounds__(256)
void attn_kernel(const float* __restrict__ key,
                 const float* __restrict__ Wk,
                 const float* __restrict__ value,
                 const int*   __restrict__ valid_lens,
                 const float* __restrict__ wv,
                 float*       __restrict__ out) {
    const int bk0 = blockIdx.x * KT;
    const int b   = bk0 >> 8;            // NK = 256
    const int t   = threadIdx.x;         // 0..255
    const int lane = t & 31;
    const int wid  = t >> 5;

    __shared__ __align__(16) float kvs[KT * H_];       // 2KB
    __shared__ __align__(16) float wvs[H_];
    __shared__ __align__(16) float shbuf[NQ_ * KT];    // 4KB: keyT then attnT
    __shared__ float redm[KT][8];
    __shared__ float gred[KT];

    const int vl = valid_lens[b];

    // ---- Prologue A: stage key rows transposed keyT[d*4 + k] ----
    {
        const int k  = t & 3;
        const int d0 = (t >> 2) * 4;     // 0..252
        float4 v = *reinterpret_cast<const float4*>(
            key + (size_t)(bk0 + k) * DK_ + d0);
        shbuf[(d0 + 0) * 4 + k] = v.x;
        shbuf[(d0 + 1) * 4 + k] = v.y;
        shbuf[(d0 + 2) * 4 + k] = v.z;
        shbuf[(d0 + 3) * 4 + k] = v.w;
        if (t < H_) wvs[t] = wv[t];
    }
    __syncthreads();

    // ---- Prologue B: kvs[k][h] = sum_d key[k][d] * Wk[d][h] ----
    {
        const int h  = t & 127;
        const int kk = (t >> 7) * 2;     // 0 or 2
        float acc0 = 0.f, acc1 = 0.f;
        const float* Wc = Wk + h;
        #pragma unroll 8
        for (int d = 0; d < DK_; ++d) {
            float w = Wc[d * H_];                                    // coalesced LDG
            float2 kp = *reinterpret_cast<const float2*>(&shbuf[d * 4 + kk]); // bcast LDS.64
            acc0 = fmaf(kp.x, w, acc0);
            acc1 = fmaf(kp.y, w, acc1);
        }
        kvs[kk * H_ + h]       = acc0;
        kvs[(kk + 1) * H_ + h] = acc1;
    }
    __syncthreads();

    float* attnT = shbuf;                // keyT dead; reuse as attnT[q*KT+k]

    // ---- Phase 1: scores + exp for q = t, all KT k (skip masked q) ----
    float e[KT];
    if (t < vl) {
        const float* qrow = g_qproj + (size_t)(b * NQ_ + t) * H_;
        float s[KT];
        #pragma unroll
        for (int k = 0; k < KT; ++k) s[k] = 0.f;

        #pragma unroll 2
        for (int h = 0; h < H_; h += 4) {
            float4 qv  = *reinterpret_cast<const float4*>(qrow + h);
            float4 wv4 = *reinterpret_cast<const float4*>(&wvs[h]);
            #pragma unroll
            for (int k = 0; k < KT; ++k) {
                float4 kv = *reinterpret_cast<const float4*>(&kvs[k * H_ + h]);
                s[k] = fmaf(wv4.x, tanh_fast(kv.x + qv.x), s[k]);
                s[k] = fmaf(wv4.y, tanh_fast(kv.y + qv.y), s[k]);
                s[k] = fmaf(wv4.z, tanh_fast(kv.z + qv.z), s[k]);
                s[k] = fmaf(wv4.w, tanh_fast(kv.w + qv.w), s[k]);
            }
        }
        #pragma unroll
        for (int k = 0; k < KT; ++k)
            e[k] = __expf(s[k]);          // |s| <= ~9, safe without max-sub
    } else {
        #pragma unroll
        for (int k = 0; k < KT; ++k) e[k] = 0.f;
    }

    // ---- Phase 2: sum-only softmax reduction per k over 256 q ----
    #pragma unroll
    for (int k = 0; k < KT; ++k) {
        float sm = e[k];
        #pragma unroll
        for (int o = 16; o > 0; o >>= 1)
            sm += __shfl_xor_sync(0xffffffffu, sm, o);
        if (lane == 0) redm[k][wid] = sm;
    }
    __syncthreads();
    if (t < 32) {                        // one warp: k = t>>3 (0..3)
        int k = t >> 3, w = t & 7;
        float v = redm[k][w];
        v += __shfl_xor_sync(0xffffffffu, v, 4);
        v += __shfl_xor_sync(0xffffffffu, v, 2);
        v += __shfl_xor_sync(0xffffffffu, v, 1);
        if (w == 0) gred[k] = v;
    }
    __syncthreads();

    {
        float4 a;
        a.x = e[0] * __frcp_rn(gred[0]);
        a.y = e[1] * __frcp_rn(gred[1]);
        a.z = e[2] * __frcp_rn(gred[2]);
        a.w = e[3] * __frcp_rn(gred[3]);
        *reinterpret_cast<float4*>(&attnT[t * KT]) = a;
    }
    __syncthreads();

    // ---- Phase 3: out[b, bk0+k, d], d = t; only q < vl contribute ----
    const float* vcol = value + (size_t)b * NQ_ * DV_ + t;
    float a0 = 0.f, a1 = 0.f, a2 = 0.f, a3 = 0.f;

    int q = 0;
    const int vl4 = vl & ~3;
    for (; q < vl4; q += 4) {
        #pragma unroll
        for (int j = 0; j < 4; ++j) {
            float v = vcol[(size_t)(q + j) * DV_];
            float4 a = *reinterpret_cast<const float4*>(&attnT[(q + j) * KT]);
            a0 = fmaf(a.x, v, a0);
            a1 = fmaf(a.y, v, a1);
            a2 = fmaf(a.z, v, a2);
            a3 = fmaf(a.w, v, a3);
        }
    }
    for (; q < vl; ++q) {
        float v = vcol[(size_t)q * DV_];
        float4 a = *reinterpret_cast<const float4*>(&attnT[q * KT]);
        a0 = fmaf(a.x, v, a0);
        a1 = fmaf(a.y, v, a1);
        a2 = fmaf(a.z, v, a2);
        a3 = fmaf(a.w, v, a3);
    }

    out[(size_t)(bk0 + 0) * DV_ + t] = a0;
    out[(size_t)(bk0 + 1) * DV_ + t] = a1;
    out[(size_t)(bk0 + 2) * DV_ + t] = a2;
    out[(size_t)(bk0 + 3) * DV_ + t] = a3;
}

// ---------------------------------------------------------------------------
extern "C" void kernel_launch(void* const* d_in, const int* in_sizes, int n_in,
                              void* d_out, int out_size) {
    const float* key        = (const float*)d_in[0];
    const float* query      = (const float*)d_in[1];
    const float* value      = (const float*)d_in[2];
    const int*   valid_lens = (const int*)  d_in[3];
    const float* Wk         = (const float*)d_in[4];
    const float* Wq         = (const float*)d_in[5];
    const float* wv         = (const float*)d_in[6];
    float* out = (float*)d_out;

    qproj_kernel<<<B_ * NQ_ / RT, 128>>>(query, Wq, valid_lens);
    attn_kernel<<<B_ * NK_ / KT, 256>>>(key, Wk, value, valid_lens, wv, out);
}